// round 2
// baseline (speedup 1.0000x reference)
#include <cuda_runtime.h>
#include <cstdint>
#include <cstddef>

#define D 128
#define MAXN 50000
#define TILE_N 64
#define TTHREADS 256
#define BN_EPS 1e-5f

// ---------------- device scratch (no allocations allowed) ----------------
__device__ float g_agg[(size_t)MAXN * D];   // aggregation buffer (reused both layers)
__device__ float g_h[(size_t)MAXN * D];     // layer-1 pre-BN output
__device__ float g_deg[MAXN];               // in-degree (float)
__device__ float g_wt1[2 * D * D];          // [k][j] transposed concat [w1_l; w1_r]
__device__ float g_wt2[2 * D * D];          // [k][j] transposed concat [w2_l; w2_r]
__device__ float g_colsum[D];
__device__ float g_colsumsq[D];
__device__ float g_scale[D];                // BN: gamma * rsqrt(var+eps)
__device__ float g_shift[D];                // BN: beta - mu*scale

// ---------------- helpers ----------------
__device__ __forceinline__ void red_add4(float* p, float4 v) {
    asm volatile("red.global.add.v4.f32 [%0], {%1,%2,%3,%4};"
                 :: "l"(p), "f"(v.x), "f"(v.y), "f"(v.z), "f"(v.w) : "memory");
}
__device__ __forceinline__ void red_add1(float* p, float v) {
    asm volatile("red.global.add.f32 [%0], %1;" :: "l"(p), "f"(v) : "memory");
}

// ---------------- weight pre-transpose: WT[k][j] = W_cat[j][k] ----------------
__global__ void prep_w_k(const float* __restrict__ w1l, const float* __restrict__ w1r,
                         const float* __restrict__ w2l, const float* __restrict__ w2r) {
    int idx = blockIdx.x * blockDim.x + threadIdx.x;
    if (idx >= 2 * D * D) return;
    int k = idx >> 7;     // 0..255
    int j = idx & 127;    // 0..127
    float v1, v2;
    if (k < D) { v1 = w1l[j * D + k];       v2 = w2l[j * D + k]; }
    else       { v1 = w1r[j * D + (k - D)]; v2 = w2r[j * D + (k - D)]; }
    g_wt1[idx] = v1;
    g_wt2[idx] = v2;
}

// ---------------- edge scatter: one warp per edge, float4 per lane ----------------
// edge_index arrives as int32 (JAX default x64-disabled downcasts the int64 ask)
template<bool COUNT, bool BN>
__global__ void scatter_k(const float* __restrict__ feat,
                          const int* __restrict__ ei, int E) {
    int lane  = threadIdx.x & 31;
    int warp  = (blockIdx.x * blockDim.x + threadIdx.x) >> 5;
    int nwarp = (gridDim.x * blockDim.x) >> 5;
    float4 sc, sh;
    if (BN) {
        sc = __ldg((const float4*)g_scale + lane);
        sh = __ldg((const float4*)g_shift + lane);
    }
    for (int e = warp; e < E; e += nwarp) {
        int s = __ldg(ei + e);
        int d = __ldg(ei + E + e);
        float4 v = __ldg((const float4*)(feat + (size_t)s * D) + lane);
        if (BN) {  // relu(bn(h_pre)) applied on the fly during gather
            v.x = fmaxf(fmaf(v.x, sc.x, sh.x), 0.f);
            v.y = fmaxf(fmaf(v.y, sc.y, sh.y), 0.f);
            v.z = fmaxf(fmaf(v.z, sc.z, sh.z), 0.f);
            v.w = fmaxf(fmaf(v.w, sc.w, sh.w), 0.f);
        }
        red_add4(g_agg + (size_t)d * D + lane * 4, v);
        if (COUNT && lane == 0) red_add1(g_deg + d, 1.0f);
    }
}

// ---------------- node transform: out = [mean || self] @ WT + bias ----------------
// persistent grid; smem = sIn[64][256] + sW[256][128] = 192KB, 1 CTA/SM
// warp layout: all 32 lanes share one 8-node group (a-loads broadcast),
// lanes own 4 consecutive output cols (w-loads contiguous LDS.128)
template<bool STATS, bool BN_IN>
__global__ void __launch_bounds__(TTHREADS, 1)
transform_k(const float* __restrict__ inb, const float* __restrict__ bias,
            float* __restrict__ out, int nNodes, int ntiles) {
    extern __shared__ float smem[];
    float* sIn = smem;                   // [TILE_N][256]
    float* sW  = smem + TILE_N * 256;    // [256][128], k-major

    const float* wt = STATS ? g_wt1 : g_wt2;
    int tid = threadIdx.x;

    // load weights once (contiguous, coalesced, conflict-free)
    {
        const float4* w4 = (const float4*)wt;
        float4* s4 = (float4*)sW;
        #pragma unroll
        for (int i = 0; i < 32; i++)
            s4[tid + i * TTHREADS] = __ldg(w4 + tid + i * TTHREADS);
    }

    int tx = tid & 31, ty = tid >> 5;
    int j0 = tx * 4, n0 = ty * 8;
    float4 bv = __ldg((const float4*)bias + tx);

    for (int tile = blockIdx.x; tile < ntiles; tile += gridDim.x) {
        int nb = tile * TILE_N;
        __syncthreads();  // previous tile's compute done before refill

        // fill input tile: cols 0..127 = agg/deg (mean), 128..255 = self input
        #pragma unroll
        for (int i = 0; i < 16; i++) {
            int idx4 = tid + i * TTHREADS;   // 0..4095 float4 slots
            int ni = idx4 >> 6;
            int kq = idx4 & 63;
            int g = nb + ni;
            float4 v = make_float4(0.f, 0.f, 0.f, 0.f);
            if (g < nNodes) {
                if (kq < 32) {
                    float inv = 1.0f / fmaxf(__ldg(g_deg + g), 1.0f);
                    float4 a = __ldg((const float4*)(g_agg + (size_t)g * D) + kq);
                    v = make_float4(a.x * inv, a.y * inv, a.z * inv, a.w * inv);
                } else {
                    float4 b = __ldg((const float4*)(inb + (size_t)g * D) + (kq - 32));
                    if (BN_IN) {  // relu(bn(h_pre)) for the self path of layer 2
                        float4 scv = __ldg((const float4*)g_scale + (kq - 32));
                        float4 shv = __ldg((const float4*)g_shift + (kq - 32));
                        b.x = fmaxf(fmaf(b.x, scv.x, shv.x), 0.f);
                        b.y = fmaxf(fmaf(b.y, scv.y, shv.y), 0.f);
                        b.z = fmaxf(fmaf(b.z, scv.z, shv.z), 0.f);
                        b.w = fmaxf(fmaf(b.w, scv.w, shv.w), 0.f);
                    }
                    v = b;
                }
            }
            *(float4*)(sIn + ni * 256 + kq * 4) = v;
        }
        __syncthreads();

        float4 acc[8];
        #pragma unroll
        for (int r = 0; r < 8; r++) acc[r] = make_float4(0.f, 0.f, 0.f, 0.f);

        #pragma unroll 4
        for (int kb = 0; kb < 64; kb++) {
            int k = kb * 4;
            float4 w0 = *(const float4*)(sW + (k + 0) * D + j0);
            float4 w1 = *(const float4*)(sW + (k + 1) * D + j0);
            float4 w2 = *(const float4*)(sW + (k + 2) * D + j0);
            float4 w3 = *(const float4*)(sW + (k + 3) * D + j0);
            #pragma unroll
            for (int r = 0; r < 8; r++) {
                float4 a = *(const float4*)(sIn + (n0 + r) * 256 + k);
                acc[r].x = fmaf(a.x, w0.x, fmaf(a.y, w1.x, fmaf(a.z, w2.x, fmaf(a.w, w3.x, acc[r].x))));
                acc[r].y = fmaf(a.x, w0.y, fmaf(a.y, w1.y, fmaf(a.z, w2.y, fmaf(a.w, w3.y, acc[r].y))));
                acc[r].z = fmaf(a.x, w0.z, fmaf(a.y, w1.z, fmaf(a.z, w2.z, fmaf(a.w, w3.z, acc[r].z))));
                acc[r].w = fmaf(a.x, w0.w, fmaf(a.y, w1.w, fmaf(a.z, w2.w, fmaf(a.w, w3.w, acc[r].w))));
            }
        }

        // epilogue: bias, store, and (layer 1 only) BN column statistics
        float s0 = 0, s1 = 0, s2 = 0, s3 = 0;
        float q0 = 0, q1 = 0, q2 = 0, q3 = 0;
        #pragma unroll
        for (int r = 0; r < 8; r++) {
            int g = nb + n0 + r;
            if (g < nNodes) {
                float4 v = make_float4(acc[r].x + bv.x, acc[r].y + bv.y,
                                       acc[r].z + bv.z, acc[r].w + bv.w);
                *(float4*)(out + (size_t)g * D + j0) = v;
                if (STATS) {
                    s0 += v.x; q0 += v.x * v.x;
                    s1 += v.y; q1 += v.y * v.y;
                    s2 += v.z; q2 += v.z * v.z;
                    s3 += v.w; q3 += v.w * v.w;
                }
            }
        }
        if (STATS) {
            red_add1(g_colsum + j0 + 0, s0); red_add1(g_colsumsq + j0 + 0, q0);
            red_add1(g_colsum + j0 + 1, s1); red_add1(g_colsumsq + j0 + 1, q1);
            red_add1(g_colsum + j0 + 2, s2); red_add1(g_colsumsq + j0 + 2, q2);
            red_add1(g_colsum + j0 + 3, s3); red_add1(g_colsumsq + j0 + 3, q3);
        }
    }
}

// ---------------- BN finalize: per-column scale/shift ----------------
__global__ void bn_finalize_k(const float* __restrict__ gamma,
                              const float* __restrict__ beta, float invN) {
    int j = threadIdx.x;
    float mu  = g_colsum[j] * invN;
    float var = g_colsumsq[j] * invN - mu * mu;
    float sc  = gamma[j] * rsqrtf(var + BN_EPS);
    g_scale[j] = sc;
    g_shift[j] = fmaf(-mu, sc, beta[j]);
}

// ---------------- launch ----------------
extern "C" void kernel_launch(void* const* d_in, const int* in_sizes, int n_in,
                              void* d_out, int out_size) {
    const float* x     = (const float*)d_in[0];
    const int*   ei    = (const int*)d_in[1];     // int32 (JAX x64 disabled)
    const float* w1l   = (const float*)d_in[2];
    const float* b1l   = (const float*)d_in[3];
    const float* w1r   = (const float*)d_in[4];
    const float* w2l   = (const float*)d_in[5];
    const float* b2l   = (const float*)d_in[6];
    const float* w2r   = (const float*)d_in[7];
    const float* gamma = (const float*)d_in[8];
    const float* beta  = (const float*)d_in[9];
    float*       out   = (float*)d_out;

    int N = in_sizes[0] / D;
    int E = in_sizes[1] / 2;
    int ntiles = (N + TILE_N - 1) / TILE_N;

    void *p_agg, *p_deg, *p_cs, *p_cq, *p_h;
    cudaGetSymbolAddress(&p_agg, g_agg);
    cudaGetSymbolAddress(&p_deg, g_deg);
    cudaGetSymbolAddress(&p_cs,  g_colsum);
    cudaGetSymbolAddress(&p_cq,  g_colsumsq);
    cudaGetSymbolAddress(&p_h,   g_h);

    size_t smem = (size_t)(TILE_N * 256 + 256 * D) * sizeof(float);  // 192KB
    cudaFuncSetAttribute(transform_k<true,  false>,
                         cudaFuncAttributeMaxDynamicSharedMemorySize, (int)smem);
    cudaFuncSetAttribute(transform_k<false, true>,
                         cudaFuncAttributeMaxDynamicSharedMemorySize, (int)smem);

    // zero scratch (graph-capturable async memsets, default stream)
    cudaMemsetAsync(p_agg, 0, (size_t)N * D * sizeof(float));
    cudaMemsetAsync(p_deg, 0, (size_t)N * sizeof(float));
    cudaMemsetAsync(p_cs,  0, D * sizeof(float));
    cudaMemsetAsync(p_cq,  0, D * sizeof(float));

    prep_w_k<<<(2 * D * D + 255) / 256, 256>>>(w1l, w1r, w2l, w2r);

    // layer 1: aggregate x, then transform (+BN stats)
    scatter_k<true, false><<<4736, 256>>>(x, ei, E);
    transform_k<true, false><<<148, TTHREADS, smem>>>(x, b1l, (float*)p_h, N, ntiles);

    bn_finalize_k<<<1, D>>>(gamma, beta, 1.0f / (float)N);

    // layer 2: aggregate relu(bn(h)) (applied in gather), then transform
    cudaMemsetAsync(p_agg, 0, (size_t)N * D * sizeof(float));
    scatter_k<false, true><<<4736, 256>>>((const float*)p_h, ei, E);
    transform_k<false, true><<<148, TTHREADS, smem>>>((const float*)p_h, b2l, out, N, ntiles);
}

// round 3
// speedup vs baseline: 1.6074x; 1.6074x over previous
#include <cuda_runtime.h>
#include <cstdint>
#include <cstddef>

#define D 128
#define MAXN 50000
#define MAXE 800000
#define TILE_N 64
#define TTHREADS 256
#define BN_EPS 1e-5f
#define SCAN_B 1024
#define NBLK ((MAXN + SCAN_B - 1) / SCAN_B)   // 49

// ---------------- device scratch ----------------
__device__ float g_agg[(size_t)MAXN * D];   // per-node mean of neighbor features
__device__ float g_h[(size_t)MAXN * D];     // layer-1 pre-BN output
__device__ int   g_cnt[MAXN];
__device__ int   g_offs[MAXN + 1];
__device__ int   g_cur[MAXN];
__device__ int   g_bsum[NBLK];
__device__ int   g_esrc[MAXE];
__device__ float g_wt1[2 * D * D];          // [k][j] transposed [w1_l; w1_r]
__device__ float g_wt2[2 * D * D];
__device__ float g_colsum[D], g_colsumsq[D], g_scale[D], g_shift[D];

// ---------------- helpers ----------------
__device__ __forceinline__ void red_add1(float* p, float v) {
    asm volatile("red.global.add.f32 [%0], %1;" :: "l"(p), "f"(v) : "memory");
}
__device__ __forceinline__ unsigned long long fma2(unsigned long long a,
                                                   unsigned long long b,
                                                   unsigned long long c) {
    unsigned long long d;
    asm("fma.rn.f32x2 %0, %1, %2, %3;" : "=l"(d) : "l"(a), "l"(b), "l"(c));
    return d;
}
__device__ __forceinline__ unsigned long long splat2(float x) {
    unsigned long long d;
    asm("mov.b64 %0, {%1, %1};" : "=l"(d) : "f"(x));
    return d;
}
__device__ __forceinline__ void lds_v2b64(unsigned long long& a, unsigned long long& b,
                                          unsigned int addr) {
    asm("ld.shared.v2.b64 {%0, %1}, [%2];" : "=l"(a), "=l"(b) : "r"(addr));
}
__device__ __forceinline__ void lds_v4f(float& a, float& b, float& c, float& d,
                                        unsigned int addr) {
    asm("ld.shared.v4.b32 {%0, %1, %2, %3}, [%4];"
        : "=f"(a), "=f"(b), "=f"(c), "=f"(d) : "r"(addr));
}
__device__ __forceinline__ void unpack2(unsigned long long v, float& lo, float& hi) {
    asm("mov.b64 {%0, %1}, %2;" : "=f"(lo), "=f"(hi) : "l"(v));
}

// ---------------- weight pre-transpose ----------------
__global__ void prep_w_k(const float* __restrict__ w1l, const float* __restrict__ w1r,
                         const float* __restrict__ w2l, const float* __restrict__ w2r) {
    int idx = blockIdx.x * blockDim.x + threadIdx.x;
    if (idx >= 2 * D * D) return;
    int k = idx >> 7, j = idx & 127;
    float v1, v2;
    if (k < D) { v1 = w1l[j * D + k];       v2 = w2l[j * D + k]; }
    else       { v1 = w1r[j * D + (k - D)]; v2 = w2r[j * D + (k - D)]; }
    g_wt1[idx] = v1;
    g_wt2[idx] = v2;
}

// ---------------- CSR build ----------------
__global__ void hist_k(const int* __restrict__ ei, int E) {
    int e = blockIdx.x * blockDim.x + threadIdx.x;
    if (e < E) atomicAdd(&g_cnt[ei[E + e]], 1);
}

__global__ void scan_local_k(int n) {
    __shared__ int sm[SCAN_B];
    int t = threadIdx.x, i = blockIdx.x * SCAN_B + t;
    int v = (i < n) ? g_cnt[i] : 0;
    sm[t] = v; __syncthreads();
    int acc = v;
    #pragma unroll
    for (int off = 1; off < SCAN_B; off <<= 1) {
        int add = (t >= off) ? sm[t - off] : 0;
        __syncthreads();
        acc += add; sm[t] = acc;
        __syncthreads();
    }
    if (i < n) g_offs[i] = acc - v;                 // block-local exclusive
    if (t == SCAN_B - 1) g_bsum[blockIdx.x] = acc;  // block total
}

__global__ void scan_bsum_k() {
    __shared__ int sm[64];
    int t = threadIdx.x;
    int v = (t < NBLK) ? g_bsum[t] : 0;
    sm[t] = v; __syncthreads();
    int acc = v;
    #pragma unroll
    for (int off = 1; off < 64; off <<= 1) {
        int add = (t >= off) ? sm[t - off] : 0;
        __syncthreads();
        acc += add; sm[t] = acc;
        __syncthreads();
    }
    if (t < NBLK) g_bsum[t] = acc - v;              // exclusive
}

__global__ void scan_add_k(int n, int E) {
    int i = blockIdx.x * blockDim.x + threadIdx.x;
    if (i < n) {
        int o = g_offs[i] + g_bsum[i / SCAN_B];
        g_offs[i] = o;
        g_cur[i] = o;
    }
    if (i == n) g_offs[n] = E;
}

__global__ void fill_k(const int* __restrict__ ei, int E) {
    int e = blockIdx.x * blockDim.x + threadIdx.x;
    if (e < E) {
        int d = ei[E + e];
        int pos = atomicAdd(&g_cur[d], 1);
        g_esrc[pos] = ei[e];
    }
}

// ---------------- gather aggregation: one warp per node, no atomics ----------------
template<bool BN>
__global__ void gather_k(const float* __restrict__ feat, int N) {
    int gw = (blockIdx.x * blockDim.x + threadIdx.x) >> 5;
    int lane = threadIdx.x & 31;
    if (gw >= N) return;
    int s0 = g_offs[gw], s1 = g_offs[gw + 1];
    float4 sc, sh;
    if (BN) {
        sc = ((const float4*)g_scale)[lane];
        sh = ((const float4*)g_shift)[lane];
    }
    const float4* f4 = (const float4*)feat;
    float4 acc = make_float4(0.f, 0.f, 0.f, 0.f);
    int e = s0;
    for (; e + 2 <= s1; e += 2) {
        int a = g_esrc[e], b = g_esrc[e + 1];
        float4 va = __ldg(f4 + (size_t)a * 32 + lane);
        float4 vb = __ldg(f4 + (size_t)b * 32 + lane);
        if (BN) {
            va.x = fmaxf(fmaf(va.x, sc.x, sh.x), 0.f);
            va.y = fmaxf(fmaf(va.y, sc.y, sh.y), 0.f);
            va.z = fmaxf(fmaf(va.z, sc.z, sh.z), 0.f);
            va.w = fmaxf(fmaf(va.w, sc.w, sh.w), 0.f);
            vb.x = fmaxf(fmaf(vb.x, sc.x, sh.x), 0.f);
            vb.y = fmaxf(fmaf(vb.y, sc.y, sh.y), 0.f);
            vb.z = fmaxf(fmaf(vb.z, sc.z, sh.z), 0.f);
            vb.w = fmaxf(fmaf(vb.w, sc.w, sh.w), 0.f);
        }
        acc.x += va.x + vb.x; acc.y += va.y + vb.y;
        acc.z += va.z + vb.z; acc.w += va.w + vb.w;
    }
    if (e < s1) {
        int a = g_esrc[e];
        float4 va = __ldg(f4 + (size_t)a * 32 + lane);
        if (BN) {
            va.x = fmaxf(fmaf(va.x, sc.x, sh.x), 0.f);
            va.y = fmaxf(fmaf(va.y, sc.y, sh.y), 0.f);
            va.z = fmaxf(fmaf(va.z, sc.z, sh.z), 0.f);
            va.w = fmaxf(fmaf(va.w, sc.w, sh.w), 0.f);
        }
        acc.x += va.x; acc.y += va.y; acc.z += va.z; acc.w += va.w;
    }
    float inv = 1.0f / fmaxf((float)(s1 - s0), 1.0f);
    ((float4*)g_agg)[(size_t)gw * 32 + lane] =
        make_float4(acc.x * inv, acc.y * inv, acc.z * inv, acc.w * inv);
}

// ---------------- node transform: out = [mean || self] @ WT + bias (FFMA2) ----------
// smem: sInT [256][64] k-major transposed input (64KB) + sW [256][128] (128KB)
// row-pair packing: acc[p][j] b64 holds (row n0+2p, row n0+2p+1) for col j0+j
template<bool STATS, bool BN_IN>
__global__ void __launch_bounds__(TTHREADS, 1)
transform_k(const float* __restrict__ inb, const float* __restrict__ bias,
            float* __restrict__ out, int nNodes, int ntiles) {
    extern __shared__ float smem[];
    float* sInT = smem;                   // [256][TILE_N]
    float* sW   = smem + 256 * TILE_N;    // [256][128]

    const float* wt = STATS ? g_wt1 : g_wt2;
    int tid = threadIdx.x;

    // weights once, coalesced
    {
        const float4* w4 = (const float4*)wt;
        float4* s4 = (float4*)sW;
        #pragma unroll
        for (int i = 0; i < 32; i++)
            s4[tid + i * TTHREADS] = __ldg(w4 + tid + i * TTHREADS);
    }

    int tx = tid & 31, ty = tid >> 5;
    int j0 = tx * 4, n0 = ty * 8;
    float4 bv = __ldg((const float4*)bias + tx);

    unsigned int sInT_addr = (unsigned int)__cvta_generic_to_shared(sInT);
    unsigned int sW_addr   = (unsigned int)__cvta_generic_to_shared(sW);
    unsigned int aBase = sInT_addr + n0 * 4;
    unsigned int wBase = sW_addr + j0 * 4;

    // BN stats accumulated in registers across all tiles, RED once at end
    float s0 = 0, s1 = 0, s2 = 0, s3 = 0;
    float q0 = 0, q1 = 0, q2 = 0, q3 = 0;

    for (int tile = blockIdx.x; tile < ntiles; tile += gridDim.x) {
        int nb = tile * TILE_N;
        __syncthreads();

        // fill transposed tile: k rows 0..127 = mean, 128..255 = self
        #pragma unroll
        for (int i = 0; i < 16; i++) {
            int idx = tid + i * TTHREADS;   // 0..4095
            int kq = idx >> 6;              // 0..63 (quad of 256 k)
            int l  = idx & 63;              // node in tile
            int g = nb + l;
            float4 v = make_float4(0.f, 0.f, 0.f, 0.f);
            if (g < nNodes) {
                if (kq < 32) {
                    v = ((const float4*)g_agg)[(size_t)g * 32 + kq];
                } else {
                    float4 b = __ldg((const float4*)inb + (size_t)g * 32 + (kq - 32));
                    if (BN_IN) {
                        float4 scv = ((const float4*)g_scale)[kq - 32];
                        float4 shv = ((const float4*)g_shift)[kq - 32];
                        b.x = fmaxf(fmaf(b.x, scv.x, shv.x), 0.f);
                        b.y = fmaxf(fmaf(b.y, scv.y, shv.y), 0.f);
                        b.z = fmaxf(fmaf(b.z, scv.z, shv.z), 0.f);
                        b.w = fmaxf(fmaf(b.w, scv.w, shv.w), 0.f);
                    }
                    v = b;
                }
            }
            int k0 = kq * 4;
            sInT[(k0 + 0) * TILE_N + l] = v.x;
            sInT[(k0 + 1) * TILE_N + l] = v.y;
            sInT[(k0 + 2) * TILE_N + l] = v.z;
            sInT[(k0 + 3) * TILE_N + l] = v.w;
        }
        __syncthreads();

        unsigned long long acc[4][4];
        #pragma unroll
        for (int p = 0; p < 4; p++)
            #pragma unroll
            for (int j = 0; j < 4; j++) acc[p][j] = 0ULL;

        #pragma unroll 8
        for (int k = 0; k < 256; k++) {
            float w0, w1, w2, w3;
            lds_v4f(w0, w1, w2, w3, wBase + k * (D * 4));
            unsigned long long ws0 = splat2(w0), ws1 = splat2(w1),
                               ws2 = splat2(w2), ws3 = splat2(w3);
            unsigned long long p01, p23, p45, p67;
            lds_v2b64(p01, p23, aBase + k * (TILE_N * 4));
            lds_v2b64(p45, p67, aBase + k * (TILE_N * 4) + 16);
            acc[0][0] = fma2(p01, ws0, acc[0][0]);
            acc[0][1] = fma2(p01, ws1, acc[0][1]);
            acc[0][2] = fma2(p01, ws2, acc[0][2]);
            acc[0][3] = fma2(p01, ws3, acc[0][3]);
            acc[1][0] = fma2(p23, ws0, acc[1][0]);
            acc[1][1] = fma2(p23, ws1, acc[1][1]);
            acc[1][2] = fma2(p23, ws2, acc[1][2]);
            acc[1][3] = fma2(p23, ws3, acc[1][3]);
            acc[2][0] = fma2(p45, ws0, acc[2][0]);
            acc[2][1] = fma2(p45, ws1, acc[2][1]);
            acc[2][2] = fma2(p45, ws2, acc[2][2]);
            acc[2][3] = fma2(p45, ws3, acc[2][3]);
            acc[3][0] = fma2(p67, ws0, acc[3][0]);
            acc[3][1] = fma2(p67, ws1, acc[3][1]);
            acc[3][2] = fma2(p67, ws2, acc[3][2]);
            acc[3][3] = fma2(p67, ws3, acc[3][3]);
        }

        // epilogue
        #pragma unroll
        for (int p = 0; p < 4; p++) {
            float lo0, hi0, lo1, hi1, lo2, hi2, lo3, hi3;
            unpack2(acc[p][0], lo0, hi0);
            unpack2(acc[p][1], lo1, hi1);
            unpack2(acc[p][2], lo2, hi2);
            unpack2(acc[p][3], lo3, hi3);
            int g0 = nb + n0 + 2 * p;
            if (g0 < nNodes) {
                float4 v = make_float4(lo0 + bv.x, lo1 + bv.y, lo2 + bv.z, lo3 + bv.w);
                *(float4*)(out + (size_t)g0 * D + j0) = v;
                if (STATS) {
                    s0 += v.x; q0 += v.x * v.x; s1 += v.y; q1 += v.y * v.y;
                    s2 += v.z; q2 += v.z * v.z; s3 += v.w; q3 += v.w * v.w;
                }
            }
            if (g0 + 1 < nNodes) {
                float4 v = make_float4(hi0 + bv.x, hi1 + bv.y, hi2 + bv.z, hi3 + bv.w);
                *(float4*)(out + (size_t)(g0 + 1) * D + j0) = v;
                if (STATS) {
                    s0 += v.x; q0 += v.x * v.x; s1 += v.y; q1 += v.y * v.y;
                    s2 += v.z; q2 += v.z * v.z; s3 += v.w; q3 += v.w * v.w;
                }
            }
        }
    }

    if (STATS) {
        red_add1(g_colsum + j0 + 0, s0); red_add1(g_colsumsq + j0 + 0, q0);
        red_add1(g_colsum + j0 + 1, s1); red_add1(g_colsumsq + j0 + 1, q1);
        red_add1(g_colsum + j0 + 2, s2); red_add1(g_colsumsq + j0 + 2, q2);
        red_add1(g_colsum + j0 + 3, s3); red_add1(g_colsumsq + j0 + 3, q3);
    }
}

// ---------------- BN finalize ----------------
__global__ void bn_finalize_k(const float* __restrict__ gamma,
                              const float* __restrict__ beta, float invN) {
    int j = threadIdx.x;
    float mu  = g_colsum[j] * invN;
    float var = g_colsumsq[j] * invN - mu * mu;
    float sc  = gamma[j] * rsqrtf(var + BN_EPS);
    g_scale[j] = sc;
    g_shift[j] = fmaf(-mu, sc, beta[j]);
}

// ---------------- launch ----------------
extern "C" void kernel_launch(void* const* d_in, const int* in_sizes, int n_in,
                              void* d_out, int out_size) {
    const float* x     = (const float*)d_in[0];
    const int*   ei    = (const int*)d_in[1];     // int32
    const float* w1l   = (const float*)d_in[2];
    const float* b1l   = (const float*)d_in[3];
    const float* w1r   = (const float*)d_in[4];
    const float* w2l   = (const float*)d_in[5];
    const float* b2l   = (const float*)d_in[6];
    const float* w2r   = (const float*)d_in[7];
    const float* gamma = (const float*)d_in[8];
    const float* beta  = (const float*)d_in[9];
    float*       out   = (float*)d_out;

    int N = in_sizes[0] / D;
    int E = in_sizes[1] / 2;
    int ntiles = (N + TILE_N - 1) / TILE_N;

    void *p_cnt, *p_cs, *p_cq, *p_h;
    cudaGetSymbolAddress(&p_cnt, g_cnt);
    cudaGetSymbolAddress(&p_cs,  g_colsum);
    cudaGetSymbolAddress(&p_cq,  g_colsumsq);
    cudaGetSymbolAddress(&p_h,   g_h);

    size_t smem = (size_t)(256 * TILE_N + 256 * D) * sizeof(float);  // 192KB
    cudaFuncSetAttribute(transform_k<true,  false>,
                         cudaFuncAttributeMaxDynamicSharedMemorySize, (int)smem);
    cudaFuncSetAttribute(transform_k<false, true>,
                         cudaFuncAttributeMaxDynamicSharedMemorySize, (int)smem);

    cudaMemsetAsync(p_cnt, 0, (size_t)N * sizeof(int));
    cudaMemsetAsync(p_cs,  0, D * sizeof(float));
    cudaMemsetAsync(p_cq,  0, D * sizeof(float));

    prep_w_k<<<(2 * D * D + 255) / 256, 256>>>(w1l, w1r, w2l, w2r);

    // CSR build (reused by both layers)
    int egrid = (E + 255) / 256;
    hist_k<<<egrid, 256>>>(ei, E);
    scan_local_k<<<(N + SCAN_B - 1) / SCAN_B, SCAN_B>>>(N);
    scan_bsum_k<<<1, 64>>>();
    scan_add_k<<<(N + 256) / 256, 256>>>(N, E);
    fill_k<<<egrid, 256>>>(ei, E);

    int ggrid = (N * 32 + 255) / 256;

    // layer 1
    gather_k<false><<<ggrid, 256>>>(x, N);
    transform_k<true, false><<<148, TTHREADS, smem>>>(x, b1l, (float*)p_h, N, ntiles);

    bn_finalize_k<<<1, D>>>(gamma, beta, 1.0f / (float)N);

    // layer 2 (relu∘bn fused into gather + self-path load)
    gather_k<true><<<ggrid, 256>>>((const float*)p_h, N);
    transform_k<false, true><<<148, TTHREADS, smem>>>((const float*)p_h, b2l, out, N, ntiles);
}